// round 14
// baseline (speedup 1.0000x reference)
#include <cuda_runtime.h>
#include <cuda_fp16.h>
#include <cstdint>

#define NUM_EXPERT 16
#define IN_FEAT 1024
#define OUT_FEAT 1024
#define BATCH 8192

#define BM 128
#define BN 128
#define BK 128
#define NCHUNK (IN_FEAT / BK)    // 8
#define THREADS 256
#define SPAD 136                 // fp16 per A smem row (128 data + 8 pad)
#define ROWB (SPAD * 2)          // 272 B
#define ASTAGE (BM * ROWB)       // 34816
#define NSTAGE 2
#define SMEM_TILES 512
#define SMEM_TOTAL (SMEM_TILES + NSTAGE * ASTAGE)   // 70144

#define NPERS 296                // 148 SMs x 2 CTAs
#define WBLOCKS (NUM_EXPERT * OUT_FEAT * IN_FEAT / 2 / 4 / 256)  // 8192
#define ABLOCKS (BATCH * IN_FEAT / 8 / 256)                      // 1024

__device__ int g_counts[NUM_EXPERT + 1];   // [16] = persistent work counter
__device__ int g_rows[NUM_EXPERT * BATCH];
// W in HMMA B-fragment layout: [e][ntile(32)][half32k(32)][j(4)][lane(32)] uint4
__device__ uint4 g_wf[NUM_EXPERT * 32 * 32 * 128];               // 33.5 MB
__device__ __align__(16) unsigned short g_ahi[BATCH * IN_FEAT];  // 16.8 MB

// ---------------- helpers ----------------
__device__ __forceinline__ uint32_t smem_u32(const void* p) {
    uint32_t a;
    asm("{ .reg .u64 t; cvta.to.shared.u64 t, %1; cvt.u32.u64 %0, t; }" : "=r"(a) : "l"(p));
    return a;
}
__device__ __forceinline__ uint32_t pack_h2(float x, float y) {
    uint32_t r;
    asm("cvt.rn.f16x2.f32 %0, %1, %2;" : "=r"(r) : "f"(y), "f"(x));
    return r;
}
__device__ __forceinline__ void cp16(uint32_t dst, const void* src, uint32_t bytes) {
    asm volatile("cp.async.cg.shared.global [%0], [%1], 16, %2;"
                 :: "r"(dst), "l"(src), "r"(bytes) : "memory");
}
__device__ __forceinline__ void cp_commit() {
    asm volatile("cp.async.commit_group;" ::: "memory");
}
template <int N>
__device__ __forceinline__ void cp_wait() {
    asm volatile("cp.async.wait_group %0;" :: "n"(N) : "memory");
}
__device__ __forceinline__ void ldsm4(uint32_t* r, uint32_t addr) {
    asm volatile("ldmatrix.sync.aligned.m8n8.x4.shared.b16 {%0,%1,%2,%3}, [%4];"
                 : "=r"(r[0]), "=r"(r[1]), "=r"(r[2]), "=r"(r[3]) : "r"(addr));
}
__device__ __forceinline__ void mma16816(float* d, const uint32_t* a, const uint32_t* b) {
    asm volatile(
        "mma.sync.aligned.m16n8k16.row.col.f32.f16.f16.f32 "
        "{%0,%1,%2,%3}, {%4,%5,%6,%7}, {%8,%9}, {%0,%1,%2,%3};"
        : "+f"(d[0]), "+f"(d[1]), "+f"(d[2]), "+f"(d[3])
        : "r"(a[0]), "r"(a[1]), "r"(a[2]), "r"(a[3]), "r"(b[0]), "r"(b[1]));
}

// ---------------- fused prepass: W permute + A convert + routing ----------------
__global__ __launch_bounds__(256)
void convert_all_kernel(const float* __restrict__ w,
                        const float* __restrict__ a,
                        const int* __restrict__ gate) {
    if (blockIdx.x < WBLOCKS) {
        int t = blockIdx.x * 256 + threadIdx.x;
        int l = t & 31, j = (t >> 5) & 3, c = (t >> 7) & 31;
        int nt = (t >> 12) & 31, e = t >> 17;
        int ks = j >> 1;
        int kbase = c * 32 + ks * 16 + (l & 3) * 2;
        uint4 d;
        uint32_t* dq = (uint32_t*)&d;
        #pragma unroll
        for (int q = 0; q < 4; q++) {
            int n = nt * 32 + ((j & 1) * 2 + (q >> 1)) * 8 + (l >> 2);
            int k = kbase + (q & 1) * 8;
            float2 v = *reinterpret_cast<const float2*>(
                w + (((size_t)e << 10) + n) * IN_FEAT + k);
            dq[q] = pack_h2(v.x, v.y);
        }
        g_wf[t] = d;
    } else {
        int b = blockIdx.x - WBLOCKS;
        int jj = b * 256 + threadIdx.x;
        if (jj < BATCH) {
            int e = gate[jj];
            int pos = atomicAdd(&g_counts[e], 1);
            g_rows[e * BATCH + pos] = jj;
        }
        int i = jj * 2;
        #pragma unroll
        for (int q = 0; q < 2; q++) {
            float4 v = reinterpret_cast<const float4*>(a)[i + q];
            reinterpret_cast<uint2*>(g_ahi)[i + q] =
                make_uint2(pack_h2(v.x, v.y), pack_h2(v.z, v.w));
        }
    }
}

// ---------------- persistent grouped GEMM: atomic work queue ----------------
__global__ __launch_bounds__(THREADS, 2)
void moe_mma_kernel(float* __restrict__ out) {
    extern __shared__ char smem[];
    int* srows = (int*)smem;
    int* sitem = (int*)(smem + 496);

    const int tid = threadIdx.x;
    const int wid = tid >> 5;
    const int lane = tid & 31;
    const int warp_m = wid >> 2;      // 0..1 -> 64-row half
    const int warp_n = wid & 3;       // 0..3 -> 32-col quarter

    // total work items = 8 * sum(ceil(cnt_e/128))
    int total = 0;
    #pragma unroll
    for (int i = 0; i < NUM_EXPERT; i++)
        total += (g_counts[i] + BM - 1) >> 7;
    total <<= 3;

    const uint32_t TILES = smem_u32(smem) + SMEM_TILES;
    const int m0 = tid >> 4;
    const int kq = tid & 15;
    const uint32_t a_dst0 = (uint32_t)(m0 * ROWB + kq * 16);
    const unsigned short* a_base = g_ahi + kq * 8;
    const uint32_t a_off =
        (uint32_t)((warp_m * 64 + (lane & 15)) * SPAD + ((lane >> 4) << 3)) * 2;

    while (true) {
        __syncthreads();            // previous item fully done (epilogue + reads)
        if (tid == 0) *sitem = atomicAdd(&g_counts[NUM_EXPERT], 1);
        __syncthreads();
        const int item = *sitem;
        if (item >= total) return;

        const int ty = item >> 3;
        const int nx = item & 7;

        int e = 0, tt = 0, cnt = 0;
        {
            int n = 0;
            bool found = false;
            #pragma unroll
            for (int i = 0; i < NUM_EXPERT; i++) {
                int ci = g_counts[i];
                int nti = (ci + BM - 1) >> 7;
                if (!found && ty < n + nti) { e = i; tt = ty - n; cnt = ci; found = true; }
                n += nti;
            }
        }
        const int row0 = tt * BM;
        const int col0 = nx * BN;

        if (tid < BM) {
            int r = row0 + tid;
            srows[tid] = (r < cnt) ? g_rows[e * BATCH + r] : -1;
        }
        __syncthreads();

        const uint4* wq = g_wf +
            ((size_t)((e * 32 + nx * 4 + warp_n) * 32)) * 128 + lane;

        float acc[4][4][4];
        #pragma unroll
        for (int mt = 0; mt < 4; mt++)
            #pragma unroll
            for (int nt = 0; nt < 4; nt++)
                #pragma unroll
                for (int q = 0; q < 4; q++) acc[mt][nt][q] = 0.0f;

        // ---- prologue: A chunk 0 into stage 0, W half 0 into wbuf[0]
        #pragma unroll
        for (int i = 0; i < 8; i++) {
            int r = srows[m0 + 16 * i];
            cp16(TILES + a_dst0 + (uint32_t)i * (16 * ROWB),
                 a_base + ((size_t)(r < 0 ? 0 : r) << 10), (r >= 0) ? 16u : 0u);
        }
        cp_commit();

        uint32_t wbuf[2][16];
        #pragma unroll
        for (int j = 0; j < 4; j++) {
            uint4 t = __ldg(wq + j * 32);
            wbuf[0][j * 4 + 0] = t.x; wbuf[0][j * 4 + 1] = t.y;
            wbuf[0][j * 4 + 2] = t.z; wbuf[0][j * 4 + 3] = t.w;
        }

        #pragma unroll 1
        for (int c = 0; c < NCHUNK; c++) {
            cp_wait<0>();
            __syncthreads();

            if (c + 1 < NCHUNK) {
                uint32_t base = TILES + (uint32_t)((c + 1) & 1) * ASTAGE;
                const unsigned short* ap = a_base + (c + 1) * BK;
                #pragma unroll
                for (int i = 0; i < 8; i++) {
                    int r = srows[m0 + 16 * i];
                    cp16(base + a_dst0 + (uint32_t)i * (16 * ROWB),
                         ap + ((size_t)(r < 0 ? 0 : r) << 10), (r >= 0) ? 16u : 0u);
                }
            }
            cp_commit();

            const uint32_t soff = TILES + (uint32_t)(c & 1) * ASTAGE;

            #pragma unroll
            for (int h = 0; h < 4; h++) {
                const int g = 4 * c + h;
                if (g + 1 < 32) {
                    #pragma unroll
                    for (int j = 0; j < 4; j++) {
                        uint4 t = __ldg(wq + (size_t)(g + 1) * 128 + j * 32);
                        wbuf[(h + 1) & 1][j * 4 + 0] = t.x;
                        wbuf[(h + 1) & 1][j * 4 + 1] = t.y;
                        wbuf[(h + 1) & 1][j * 4 + 2] = t.z;
                        wbuf[(h + 1) & 1][j * 4 + 3] = t.w;
                    }
                }
                #pragma unroll
                for (int ks = 0; ks < 2; ks++) {
                    #pragma unroll
                    for (int mt = 0; mt < 4; mt++) {
                        uint32_t a_[4];
                        ldsm4(a_, soff + a_off + h * 64 + ks * 32 + mt * (16 * ROWB));
                        #pragma unroll
                        for (int nt = 0; nt < 4; nt++)
                            mma16816(acc[mt][nt], a_,
                                     &wbuf[h & 1][(ks * 2 + (nt >> 1)) * 4 + (nt & 1) * 2]);
                    }
                }
            }
        }

        // ---- epilogue
        const int rbase = warp_m * 64 + (lane >> 2);
        const int cbase = col0 + warp_n * 32 + (lane & 3) * 2;
        #pragma unroll
        for (int mt = 0; mt < 4; mt++) {
            int r0 = srows[rbase + mt * 16];
            int r1 = srows[rbase + mt * 16 + 8];
            #pragma unroll
            for (int nt = 0; nt < 4; nt++) {
                int col = cbase + nt * 8;
                if (r0 >= 0)
                    *reinterpret_cast<float2*>(out + (size_t)r0 * OUT_FEAT + col) =
                        make_float2(acc[mt][nt][0], acc[mt][nt][1]);
                if (r1 >= 0)
                    *reinterpret_cast<float2*>(out + (size_t)r1 * OUT_FEAT + col) =
                        make_float2(acc[mt][nt][2], acc[mt][nt][3]);
            }
        }
    }
}

extern "C" void kernel_launch(void* const* d_in, const int* in_sizes, int n_in,
                              void* d_out, int out_size) {
    const float* inp    = (const float*)d_in[0];   // [8192, 1024] f32
    const int*   gate   = (const int*)d_in[1];     // [8192] i32
    const float* weight = (const float*)d_in[2];   // [16, 1024, 1024] f32
    float* out = (float*)d_out;                    // [8192, 1024] f32

    cudaFuncSetAttribute(moe_mma_kernel, cudaFuncAttributeMaxDynamicSharedMemorySize,
                         SMEM_TOTAL);

    void* counts_ptr = nullptr;
    cudaGetSymbolAddress(&counts_ptr, g_counts);
    cudaMemsetAsync(counts_ptr, 0, (NUM_EXPERT + 1) * sizeof(int));

    convert_all_kernel<<<WBLOCKS + ABLOCKS, 256>>>(weight, inp, gate);

    moe_mma_kernel<<<NPERS, THREADS, SMEM_TOTAL>>>(out);
}

// round 15
// speedup vs baseline: 1.0184x; 1.0184x over previous
#include <cuda_runtime.h>
#include <cuda_fp16.h>
#include <cstdint>

#define NUM_EXPERT 16
#define IN_FEAT 1024
#define OUT_FEAT 1024
#define BATCH 8192

#define BM 128
#define BN 128
#define BK 128
#define NCHUNK (IN_FEAT / BK)    // 8
#define THREADS 256
#define SPAD 136                 // fp16 per A smem row (128 data + 8 pad)
#define ROWB (SPAD * 2)          // 272 B
#define ASTAGE (BM * ROWB)       // 34816
#define NSTAGE 3
#define SMEM_TILES 512
#define SMEM_TOTAL (SMEM_TILES + NSTAGE * ASTAGE)   // 104960

#define MAX_TILES 79
#define WBLOCKS (NUM_EXPERT * OUT_FEAT * IN_FEAT / 2 / 4 / 256)  // 8192
#define ABLOCKS (BATCH * IN_FEAT / 8 / 256)                      // 1024

__device__ int g_counts[NUM_EXPERT];
__device__ int g_rows[NUM_EXPERT * BATCH];
// W in HMMA B-fragment layout: [e][ntile(32)][half32k(32)][j(4)][lane(32)] uint4
__device__ uint4 g_wf[NUM_EXPERT * 32 * 32 * 128];               // 33.5 MB
__device__ __align__(16) unsigned short g_ahi[BATCH * IN_FEAT];  // 16.8 MB

// ---------------- helpers ----------------
__device__ __forceinline__ uint32_t smem_u32(const void* p) {
    uint32_t a;
    asm("{ .reg .u64 t; cvta.to.shared.u64 t, %1; cvt.u32.u64 %0, t; }" : "=r"(a) : "l"(p));
    return a;
}
__device__ __forceinline__ uint32_t pack_h2(float x, float y) {
    uint32_t r;
    asm("cvt.rn.f16x2.f32 %0, %1, %2;" : "=r"(r) : "f"(y), "f"(x));
    return r;
}
__device__ __forceinline__ void cp16(uint32_t dst, const void* src, uint32_t bytes) {
    asm volatile("cp.async.cg.shared.global [%0], [%1], 16, %2;"
                 :: "r"(dst), "l"(src), "r"(bytes) : "memory");
}
__device__ __forceinline__ void cp_commit() {
    asm volatile("cp.async.commit_group;" ::: "memory");
}
template <int N>
__device__ __forceinline__ void cp_wait() {
    asm volatile("cp.async.wait_group %0;" :: "n"(N) : "memory");
}
__device__ __forceinline__ void ldsm4(uint32_t* r, uint32_t addr) {
    asm volatile("ldmatrix.sync.aligned.m8n8.x4.shared.b16 {%0,%1,%2,%3}, [%4];"
                 : "=r"(r[0]), "=r"(r[1]), "=r"(r[2]), "=r"(r[3]) : "r"(addr));
}
__device__ __forceinline__ void mma16816(float* d, const uint32_t* a, const uint32_t* b) {
    asm volatile(
        "mma.sync.aligned.m16n8k16.row.col.f32.f16.f16.f32 "
        "{%0,%1,%2,%3}, {%4,%5,%6,%7}, {%8,%9}, {%0,%1,%2,%3};"
        : "+f"(d[0]), "+f"(d[1]), "+f"(d[2]), "+f"(d[3])
        : "r"(a[0]), "r"(a[1]), "r"(a[2]), "r"(a[3]), "r"(b[0]), "r"(b[1]));
}

// ---------------- fused prepass: W permute + A convert + routing ----------------
__global__ __launch_bounds__(256)
void convert_all_kernel(const float* __restrict__ w,
                        const float* __restrict__ a,
                        const int* __restrict__ gate) {
    if (blockIdx.x < WBLOCKS) {
        int t = blockIdx.x * 256 + threadIdx.x;
        int l = t & 31, j = (t >> 5) & 3, c = (t >> 7) & 31;
        int nt = (t >> 12) & 31, e = t >> 17;
        int ks = j >> 1;
        int kbase = c * 32 + ks * 16 + (l & 3) * 2;
        uint4 d;
        uint32_t* dq = (uint32_t*)&d;
        #pragma unroll
        for (int q = 0; q < 4; q++) {
            int n = nt * 32 + ((j & 1) * 2 + (q >> 1)) * 8 + (l >> 2);
            int k = kbase + (q & 1) * 8;
            float2 v = *reinterpret_cast<const float2*>(
                w + (((size_t)e << 10) + n) * IN_FEAT + k);
            dq[q] = pack_h2(v.x, v.y);
        }
        g_wf[t] = d;
    } else {
        int b = blockIdx.x - WBLOCKS;
        int jj = b * 256 + threadIdx.x;
        if (jj < BATCH) {
            int e = gate[jj];
            int pos = atomicAdd(&g_counts[e], 1);
            g_rows[e * BATCH + pos] = jj;
        }
        int i = jj * 2;
        #pragma unroll
        for (int q = 0; q < 2; q++) {
            float4 v = reinterpret_cast<const float4*>(a)[i + q];
            reinterpret_cast<uint2*>(g_ahi)[i + q] =
                make_uint2(pack_h2(v.x, v.y), pack_h2(v.z, v.w));
        }
    }
}

// ---------------- grouped GEMM: BK=128, 3-stage A, ldsm pipeline ----------------
__global__ __launch_bounds__(THREADS, 2)
void moe_mma_kernel(float* __restrict__ out) {
    const int ty = blockIdx.y;
    int e = -1, tt = 0, cnt = 0;
    {
        int n = 0;
        #pragma unroll
        for (int i = 0; i < NUM_EXPERT; i++) {
            int ci = g_counts[i];
            int nti = (ci + BM - 1) >> 7;
            if (e < 0 && ty < n + nti) { e = i; tt = ty - n; cnt = ci; }
            n += nti;
        }
    }
    if (e < 0) return;
    const int row0 = tt * BM;
    const int col0 = blockIdx.x * BN;

    extern __shared__ char smem[];
    int* srows = (int*)smem;

    const int tid = threadIdx.x;
    const int wid = tid >> 5;
    const int lane = tid & 31;
    const int warp_m = wid >> 2;      // 0..1 -> 64-row half
    const int warp_n = wid & 3;       // 0..3 -> 32-col quarter

    if (tid < BM) {
        int r = row0 + tid;
        srows[tid] = (r < cnt) ? g_rows[e * BATCH + r] : -1;
    }
    __syncthreads();

    const uint32_t TILES = smem_u32(smem) + SMEM_TILES;

    // ---- A cp.async geometry: 8 x 16B per thread per chunk
    const int m0 = tid >> 4;
    const int kq = tid & 15;
    const uint32_t a_dst0 = (uint32_t)(m0 * ROWB + kq * 16);
    const unsigned short* a_base = g_ahi + kq * 8;

    // ---- W fragment pointer (32k-half granularity)
    const uint4* wq = g_wf +
        ((size_t)((e * 32 + blockIdx.x * 4 + warp_n) * 32)) * 128 + lane;

    // ---- A ldsm per-lane offset
    const uint32_t a_off =
        (uint32_t)((warp_m * 64 + (lane & 15)) * SPAD + ((lane >> 4) << 3)) * 2;

    float acc[4][4][4];
    #pragma unroll
    for (int mt = 0; mt < 4; mt++)
        #pragma unroll
        for (int nt = 0; nt < 4; nt++)
            #pragma unroll
            for (int q = 0; q < 4; q++) acc[mt][nt][q] = 0.0f;

    // ---- prologue: A chunks 0,1 into stages 0,1; W half 0 into wbuf[0]
    #pragma unroll
    for (int s = 0; s < NSTAGE - 1; s++) {
        uint32_t base = TILES + (uint32_t)s * ASTAGE;
        const unsigned short* ap = a_base + s * BK;
        #pragma unroll
        for (int i = 0; i < 8; i++) {
            int r = srows[m0 + 16 * i];
            cp16(base + a_dst0 + (uint32_t)i * (16 * ROWB),
                 ap + ((size_t)(r < 0 ? 0 : r) << 10), (r >= 0) ? 16u : 0u);
        }
        cp_commit();
    }

    uint32_t wbuf[2][16];
    #pragma unroll
    for (int j = 0; j < 4; j++) {
        uint4 t = __ldg(wq + j * 32);
        wbuf[0][j * 4 + 0] = t.x; wbuf[0][j * 4 + 1] = t.y;
        wbuf[0][j * 4 + 2] = t.z; wbuf[0][j * 4 + 3] = t.w;
    }

    #pragma unroll 1
    for (int c = 0; c < NCHUNK; c++) {
        cp_wait<1>();               // chunk c landed (c+1 may still be in flight)
        __syncthreads();            // all warps done with stage (c-1): safe to refill

        const int cn = c + NSTAGE - 1;
        if (cn < NCHUNK) {
            uint32_t base = TILES + (uint32_t)(cn % NSTAGE) * ASTAGE;
            const unsigned short* ap = a_base + cn * BK;
            #pragma unroll
            for (int i = 0; i < 8; i++) {
                int r = srows[m0 + 16 * i];
                cp16(base + a_dst0 + (uint32_t)i * (16 * ROWB),
                     ap + ((size_t)(r < 0 ? 0 : r) << 10), (r >= 0) ? 16u : 0u);
            }
        }
        cp_commit();

        const uint32_t soff = TILES + (uint32_t)(c % NSTAGE) * ASTAGE + a_off;

        // 4 W-halves per chunk; prefetch W half h+1 and pipeline A ldsm (p -> p+1)
        #pragma unroll
        for (int h = 0; h < 4; h++) {
            const int g = 4 * c + h;
            if (g + 1 < 32) {
                #pragma unroll
                for (int j = 0; j < 4; j++) {
                    uint4 t = __ldg(wq + (size_t)(g + 1) * 128 + j * 32);
                    wbuf[(h + 1) & 1][j * 4 + 0] = t.x;
                    wbuf[(h + 1) & 1][j * 4 + 1] = t.y;
                    wbuf[(h + 1) & 1][j * 4 + 2] = t.z;
                    wbuf[(h + 1) & 1][j * 4 + 3] = t.w;
                }
            }
            // 8 fragment positions p = ks*4+mt; prefetch p+1 during p's MMAs
            uint32_t afr[2][4];
            ldsm4(afr[0], soff + h * 64);           // p = 0 (ks=0, mt=0)
            #pragma unroll
            for (int p = 0; p < 8; p++) {
                const int ks = p >> 2, mt = p & 3;
                if (p + 1 < 8) {
                    const int pn = p + 1;
                    ldsm4(afr[(p + 1) & 1],
                          soff + h * 64 + (pn >> 2) * 32 + (pn & 3) * (16 * ROWB));
                }
                #pragma unroll
                for (int nt = 0; nt < 4; nt++)
                    mma16816(acc[mt][nt], afr[p & 1],
                             &wbuf[h & 1][(ks * 2 + (nt >> 1)) * 4 + (nt & 1) * 2]);
            }
        }
    }

    // ---- epilogue
    const int rbase = warp_m * 64 + (lane >> 2);
    const int cbase = col0 + warp_n * 32 + (lane & 3) * 2;
    #pragma unroll
    for (int mt = 0; mt < 4; mt++) {
        int r0 = srows[rbase + mt * 16];
        int r1 = srows[rbase + mt * 16 + 8];
        #pragma unroll
        for (int nt = 0; nt < 4; nt++) {
            int col = cbase + nt * 8;
            if (r0 >= 0)
                *reinterpret_cast<float2*>(out + (size_t)r0 * OUT_FEAT + col) =
                    make_float2(acc[mt][nt][0], acc[mt][nt][1]);
            if (r1 >= 0)
                *reinterpret_cast<float2*>(out + (size_t)r1 * OUT_FEAT + col) =
                    make_float2(acc[mt][nt][2], acc[mt][nt][3]);
        }
    }
}

extern "C" void kernel_launch(void* const* d_in, const int* in_sizes, int n_in,
                              void* d_out, int out_size) {
    const float* inp    = (const float*)d_in[0];   // [8192, 1024] f32
    const int*   gate   = (const int*)d_in[1];     // [8192] i32
    const float* weight = (const float*)d_in[2];   // [16, 1024, 1024] f32
    float* out = (float*)d_out;                    // [8192, 1024] f32

    cudaFuncSetAttribute(moe_mma_kernel, cudaFuncAttributeMaxDynamicSharedMemorySize,
                         SMEM_TOTAL);

    void* counts_ptr = nullptr;
    cudaGetSymbolAddress(&counts_ptr, g_counts);
    cudaMemsetAsync(counts_ptr, 0, NUM_EXPERT * sizeof(int));

    convert_all_kernel<<<WBLOCKS + ABLOCKS, 256>>>(weight, inp, gate);

    dim3 grid(OUT_FEAT / BN, MAX_TILES, 1);
    moe_mma_kernel<<<grid, THREADS, SMEM_TOTAL>>>(out);
}